// round 1
// baseline (speedup 1.0000x reference)
#include <cuda_runtime.h>
#include <math.h>

#define B_ 4
#define S_ 2048
#define HID_ 1024
#define NH_ 16
#define HD_ 64

// Scratch for Q, K, V in [B*NH, S, HD] layout (32 MB each).
__device__ float g_q[B_ * NH_ * S_ * HD_];
__device__ float g_k[B_ * NH_ * S_ * HD_];
__device__ float g_v[B_ * NH_ * S_ * HD_];

// ---------------------------------------------------------------------------
// QKV projection: out[p] = H @ W[p]^T + b[p], reshaped to [B,NH,S,HD].
// H: [8192, 1024] row-major. W: [1024, 1024] row-major (n, k).
// Tiles: BM=64, BN=64, BK=16; 256 threads; 4x4 microtile per thread.
// ---------------------------------------------------------------------------
__global__ __launch_bounds__(256) void qkv_gemm(
    const float* __restrict__ H,
    const float* __restrict__ Wq, const float* __restrict__ bq,
    const float* __restrict__ Wk, const float* __restrict__ bk,
    const float* __restrict__ Wv, const float* __restrict__ bv)
{
    __shared__ float As[16][68];  // [k][m]
    __shared__ float Bs[16][68];  // [k][n]

    const int proj = blockIdx.z;
    const float* W    = (proj == 0) ? Wq : (proj == 1) ? Wk : Wv;
    const float* bias = (proj == 0) ? bq : (proj == 1) ? bk : bv;
    float* out        = (proj == 0) ? g_q : (proj == 1) ? g_k : g_v;

    const int m0 = blockIdx.y * 64;
    const int n0 = blockIdx.x * 64;
    const int t  = threadIdx.x;
    const int tx = t & 15;
    const int ty = t >> 4;
    const int lrow = t >> 2;          // 0..63
    const int lk   = (t & 3) * 4;     // 0,4,8,12

    float acc[4][4] = {};

    for (int k0 = 0; k0 < HID_; k0 += 16) {
        float4 a = *(const float4*)(H + (size_t)(m0 + lrow) * HID_ + k0 + lk);
        float4 w = *(const float4*)(W + (size_t)(n0 + lrow) * HID_ + k0 + lk);
        __syncthreads();
        As[lk + 0][lrow] = a.x; As[lk + 1][lrow] = a.y;
        As[lk + 2][lrow] = a.z; As[lk + 3][lrow] = a.w;
        Bs[lk + 0][lrow] = w.x; Bs[lk + 1][lrow] = w.y;
        Bs[lk + 2][lrow] = w.z; Bs[lk + 3][lrow] = w.w;
        __syncthreads();
        #pragma unroll
        for (int kk = 0; kk < 16; kk++) {
            float av[4], bv4[4];
            *(float4*)av  = *(const float4*)&As[kk][ty * 4];
            *(float4*)bv4 = *(const float4*)&Bs[kk][tx * 4];
            #pragma unroll
            for (int i = 0; i < 4; i++)
                #pragma unroll
                for (int j = 0; j < 4; j++)
                    acc[i][j] += av[i] * bv4[j];
        }
    }

    // Epilogue: scatter into [B*NH, S, HD]
    const int n = n0 + tx * 4;
    const int h = n >> 6;
    const int d = n & 63;
    float4 bvec = *(const float4*)(bias + n);
    #pragma unroll
    for (int i = 0; i < 4; i++) {
        const int m  = m0 + ty * 4 + i;
        const int bb = m >> 11;       // / 2048
        const int ss = m & 2047;
        float4 o;
        o.x = acc[i][0] + bvec.x;
        o.y = acc[i][1] + bvec.y;
        o.z = acc[i][2] + bvec.z;
        o.w = acc[i][3] + bvec.w;
        *(float4*)(out + ((size_t)(bb * NH_ + h) * S_ + ss) * HD_ + d) = o;
    }
}

// ---------------------------------------------------------------------------
// Flash attention, fp32. Grid: (S/64, B*NH). 256 threads/CTA.
// Q tile 64x64 resident in smem (transposed [d][row], pre-scaled by 1/8).
// Loop over 32 KV tiles of 64: S = Q K^T (+mask), online softmax, O += P V.
// Smem: Qs,Ks ([d][col]), Vs ([k][d]), Ps ([row][k]), each 64x68 floats.
// ---------------------------------------------------------------------------
#define ATTN_SMEM (4 * 64 * 68 * 4)

extern __shared__ float s_attn[];

__global__ __launch_bounds__(256) void attn_kernel(
    const float* __restrict__ mask, float* __restrict__ out)
{
    float* Qs = s_attn;            // [d][row]
    float* Ks = Qs + 64 * 68;      // [d][col]
    float* Vs = Ks + 64 * 68;      // [k][d]
    float* Ps = Vs + 64 * 68;      // [row][k]

    const int bh = blockIdx.y;
    const int bb = bh >> 4;        // / NH
    const int h  = bh & 15;
    const int q0 = blockIdx.x * 64;

    const float* Q = g_q + (size_t)bh * S_ * HD_;
    const float* K = g_k + (size_t)bh * S_ * HD_;
    const float* V = g_v + (size_t)bh * S_ * HD_;
    const float* mrow = mask + (size_t)bb * S_;

    const int t  = threadIdx.x;
    const int tx = t & 15;
    const int ty = t >> 4;

    // Load Q tile transposed + scaled (1/sqrt(64) = 0.125)
    for (int idx = t; idx < 1024; idx += 256) {      // float4 granularity
        const int row = idx >> 4;
        const int dq  = (idx & 15) * 4;
        float4 q = *(const float4*)(Q + (size_t)(q0 + row) * HD_ + dq);
        Qs[(dq + 0) * 68 + row] = q.x * 0.125f;
        Qs[(dq + 1) * 68 + row] = q.y * 0.125f;
        Qs[(dq + 2) * 68 + row] = q.z * 0.125f;
        Qs[(dq + 3) * 68 + row] = q.w * 0.125f;
    }

    float m_i[4], l_i[4], acc_o[4][4];
    #pragma unroll
    for (int i = 0; i < 4; i++) {
        m_i[i] = -INFINITY;
        l_i[i] = 0.0f;
        #pragma unroll
        for (int j = 0; j < 4; j++) acc_o[i][j] = 0.0f;
    }

    for (int kv0 = 0; kv0 < S_; kv0 += 64) {
        __syncthreads();  // previous O-gemm done reading Vs/Ps (and Q load visible)
        // Load K (transposed [d][col]) and V ([k][d])
        for (int idx = t; idx < 1024; idx += 256) {
            const int row = idx >> 4;
            const int dq  = (idx & 15) * 4;
            float4 kv = *(const float4*)(K + (size_t)(kv0 + row) * HD_ + dq);
            Ks[(dq + 0) * 68 + row] = kv.x;
            Ks[(dq + 1) * 68 + row] = kv.y;
            Ks[(dq + 2) * 68 + row] = kv.z;
            Ks[(dq + 3) * 68 + row] = kv.w;
            float4 vv = *(const float4*)(V + (size_t)(kv0 + row) * HD_ + dq);
            *(float4*)&Vs[row * 68 + dq] = vv;
        }
        __syncthreads();

        // S-gemm: s[i][j] = sum_d Qs[d][ty*4+i] * Ks[d][tx*4+j]
        float s_acc[4][4] = {};
        #pragma unroll 8
        for (int d = 0; d < 64; d++) {
            float av[4], bv4[4];
            *(float4*)av  = *(const float4*)&Qs[d * 68 + ty * 4];
            *(float4*)bv4 = *(const float4*)&Ks[d * 68 + tx * 4];
            #pragma unroll
            for (int i = 0; i < 4; i++)
                #pragma unroll
                for (int j = 0; j < 4; j++)
                    s_acc[i][j] += av[i] * bv4[j];
        }

        // additive mask (broadcast over heads/queries)
        float mv[4];
        *(float4*)mv = *(const float4*)(mrow + kv0 + tx * 4);
        #pragma unroll
        for (int i = 0; i < 4; i++)
            #pragma unroll
            for (int j = 0; j < 4; j++)
                s_acc[i][j] += mv[j];

        // Online softmax per row (reduce across the 16-lane tx group)
        #pragma unroll
        for (int i = 0; i < 4; i++) {
            float r = fmaxf(fmaxf(s_acc[i][0], s_acc[i][1]),
                            fmaxf(s_acc[i][2], s_acc[i][3]));
            r = fmaxf(r, __shfl_xor_sync(0xffffffffu, r, 1));
            r = fmaxf(r, __shfl_xor_sync(0xffffffffu, r, 2));
            r = fmaxf(r, __shfl_xor_sync(0xffffffffu, r, 4));
            r = fmaxf(r, __shfl_xor_sync(0xffffffffu, r, 8));
            const float mnew  = fmaxf(m_i[i], r);
            const float alpha = __expf(m_i[i] - mnew);
            m_i[i] = mnew;
            float sum = 0.0f;
            #pragma unroll
            for (int j = 0; j < 4; j++) {
                s_acc[i][j] = __expf(s_acc[i][j] - mnew);
                sum += s_acc[i][j];
            }
            sum += __shfl_xor_sync(0xffffffffu, sum, 1);
            sum += __shfl_xor_sync(0xffffffffu, sum, 2);
            sum += __shfl_xor_sync(0xffffffffu, sum, 4);
            sum += __shfl_xor_sync(0xffffffffu, sum, 8);
            l_i[i] = l_i[i] * alpha + sum;
            #pragma unroll
            for (int j = 0; j < 4; j++) acc_o[i][j] *= alpha;
        }

        // Stage P to smem ([row][k]) for the O-gemm
        #pragma unroll
        for (int i = 0; i < 4; i++) {
            float4 p;
            p.x = s_acc[i][0]; p.y = s_acc[i][1];
            p.z = s_acc[i][2]; p.w = s_acc[i][3];
            *(float4*)&Ps[(ty * 4 + i) * 68 + tx * 4] = p;
        }
        __syncthreads();

        // O-gemm: o[i][j] += sum_k Ps[ty*4+i][k] * Vs[k][tx*4+j]
        #pragma unroll 4
        for (int k4 = 0; k4 < 16; k4++) {
            float pa[4][4];   // [i][kk]
            #pragma unroll
            for (int i = 0; i < 4; i++)
                *(float4*)pa[i] = *(const float4*)&Ps[(ty * 4 + i) * 68 + k4 * 4];
            float vb[4][4];   // [kk][j]
            #pragma unroll
            for (int kk = 0; kk < 4; kk++)
                *(float4*)vb[kk] = *(const float4*)&Vs[(k4 * 4 + kk) * 68 + tx * 4];
            #pragma unroll
            for (int i = 0; i < 4; i++)
                #pragma unroll
                for (int kk = 0; kk < 4; kk++)
                    #pragma unroll
                    for (int j = 0; j < 4; j++)
                        acc_o[i][j] += pa[i][kk] * vb[kk][j];
        }
    }

    // Epilogue: out[b, s, h*64+d] = O / l
    #pragma unroll
    for (int i = 0; i < 4; i++) {
        const float inv = 1.0f / l_i[i];
        float4 o;
        o.x = acc_o[i][0] * inv;
        o.y = acc_o[i][1] * inv;
        o.z = acc_o[i][2] * inv;
        o.w = acc_o[i][3] * inv;
        const int ss = q0 + ty * 4 + i;
        *(float4*)(out + ((size_t)(bb * S_ + ss) * HID_) + h * 64 + tx * 4) = o;
    }
}

// ---------------------------------------------------------------------------
extern "C" void kernel_launch(void* const* d_in, const int* in_sizes, int n_in,
                              void* d_out, int out_size)
{
    const float* H    = (const float*)d_in[0];
    const float* mask = (const float*)d_in[1];
    const float* Wq   = (const float*)d_in[2];
    const float* bq   = (const float*)d_in[3];
    const float* Wk   = (const float*)d_in[4];
    const float* bk   = (const float*)d_in[5];
    const float* Wv   = (const float*)d_in[6];
    const float* bv   = (const float*)d_in[7];
    float* out = (float*)d_out;

    cudaFuncSetAttribute(attn_kernel,
                         cudaFuncAttributeMaxDynamicSharedMemorySize, ATTN_SMEM);

    dim3 gq(HID_ / 64, (B_ * S_) / 64, 3);   // (16, 128, 3)
    qkv_gemm<<<gq, 256>>>(H, Wq, bq, Wk, bk, Wv, bv);

    dim3 ga(S_ / 64, B_ * NH_);              // (32, 64)
    attn_kernel<<<ga, 256, ATTN_SMEM>>>(mask, out);
}

// round 3
// speedup vs baseline: 1.3712x; 1.3712x over previous
#include <cuda_runtime.h>
#include <math.h>
#include <stdint.h>

#define B_ 4
#define S_ 2048
#define HID_ 1024
#define NH_ 16
#define HD_ 64

// Scratch for Q, K, V in [B*NH, S, HD] layout (32 MB each).
__device__ float g_q[B_ * NH_ * S_ * HD_];
__device__ float g_k[B_ * NH_ * S_ * HD_];
__device__ float g_v[B_ * NH_ * S_ * HD_];

// ===========================================================================
// PTX helpers (no 'a'-gated instructions: mma.sync + f32x2 only)
// ===========================================================================
__device__ __forceinline__ uint32_t f2tf32(float x) {
    uint32_t r;
    asm("cvt.rna.tf32.f32 %0, %1;" : "=r"(r) : "f"(x));
    return r;
}

__device__ __forceinline__ void mma_tf32(float* d, const uint32_t* a, const uint32_t* b) {
    asm volatile(
        "mma.sync.aligned.m16n8k8.row.col.f32.tf32.tf32.f32 "
        "{%0,%1,%2,%3}, {%4,%5,%6,%7}, {%8,%9}, {%0,%1,%2,%3};"
        : "+f"(d[0]), "+f"(d[1]), "+f"(d[2]), "+f"(d[3])
        : "r"(a[0]), "r"(a[1]), "r"(a[2]), "r"(a[3]), "r"(b[0]), "r"(b[1]));
}

// packed fp32x2 FMA (FFMA2)
__device__ __forceinline__ void ffma2(float2& d, const float2 a, const float2 b) {
    asm("fma.rn.f32x2 %0, %1, %2, %0;"
        : "+l"(*reinterpret_cast<unsigned long long*>(&d))
        : "l"(*reinterpret_cast<const unsigned long long*>(&a)),
          "l"(*reinterpret_cast<const unsigned long long*>(&b)));
}

// ===========================================================================
// QKV projection via mma.sync tf32.
// C[m,n] = sum_k H[m,k] * W[n,k]  (+ bias), scattered to [B*NH, S, HD].
// CTA tile 128x128, K staged 32. 256 threads = 8 warps (4 m x 2 n).
// Warp tile 32x64 = (2 m16) x (8 n8) mma tiles.
// Smem (tf32 bits): As[k][m] (k<32, ld 132), Bs[k][n], double buffered.
// ===========================================================================
#define BM 128
#define BN 128
#define BK 32
#define LDA 132
#define LDB 132
#define A_WORDS (BK * LDA)
#define B_WORDS (BK * LDB)
#define QKV_SMEM (2 * (A_WORDS + B_WORDS) * 4)   // 67584 B

extern __shared__ uint32_t qkv_sm[];

__global__ __launch_bounds__(256) void qkv_mma(
    const float* __restrict__ H,
    const float* __restrict__ Wq, const float* __restrict__ bq,
    const float* __restrict__ Wk, const float* __restrict__ bk,
    const float* __restrict__ Wv, const float* __restrict__ bv)
{
    const int proj = blockIdx.z;
    const float* W    = (proj == 0) ? Wq : (proj == 1) ? Wk : Wv;
    const float* bias = (proj == 0) ? bq : (proj == 1) ? bk : bv;
    float* out        = (proj == 0) ? g_q : (proj == 1) ? g_k : g_v;

    const int m0 = blockIdx.y * BM;
    const int n0 = blockIdx.x * BN;

    const int t    = threadIdx.x;
    const int lane = t & 31;
    const int wid  = t >> 5;
    const int wm   = wid & 3;       // 4 warps along M (32 rows each)
    const int wn   = wid >> 2;      // 2 warps along N (64 cols each)
    const int g    = lane >> 2;     // 0..7
    const int tig  = lane & 3;      // 0..3

    uint32_t* Abuf[2] = {qkv_sm, qkv_sm + A_WORDS};
    uint32_t* Bbuf[2] = {qkv_sm + 2 * A_WORDS, qkv_sm + 2 * A_WORDS + B_WORDS};

    float acc[2][8][4];
    #pragma unroll
    for (int i = 0; i < 2; i++)
        #pragma unroll
        for (int j = 0; j < 8; j++)
            #pragma unroll
            for (int c = 0; c < 4; c++) acc[i][j][c] = 0.0f;

    // loader: 1024 float4 per matrix per stage; 4 per thread
    const int lrow = (t >> 3);            // base row pattern via idx
    (void)lrow;

    float4 ra[4], rb[4];
    #pragma unroll
    for (int i = 0; i < 4; i++) {
        const int idx = t + i * 256;
        const int row = idx >> 3, c4 = idx & 7;
        ra[i] = *(const float4*)(H + (size_t)(m0 + row) * HID_ + c4 * 4);
        rb[i] = *(const float4*)(W + (size_t)(n0 + row) * HID_ + c4 * 4);
    }
    #pragma unroll
    for (int i = 0; i < 4; i++) {
        const int idx = t + i * 256;
        const int row = idx >> 3, c4 = idx & 7;
        const int k = c4 * 4;
        Abuf[0][(k + 0) * LDA + row] = f2tf32(ra[i].x);
        Abuf[0][(k + 1) * LDA + row] = f2tf32(ra[i].y);
        Abuf[0][(k + 2) * LDA + row] = f2tf32(ra[i].z);
        Abuf[0][(k + 3) * LDA + row] = f2tf32(ra[i].w);
        Bbuf[0][(k + 0) * LDB + row] = f2tf32(rb[i].x);
        Bbuf[0][(k + 1) * LDB + row] = f2tf32(rb[i].y);
        Bbuf[0][(k + 2) * LDB + row] = f2tf32(rb[i].z);
        Bbuf[0][(k + 3) * LDB + row] = f2tf32(rb[i].w);
    }
    __syncthreads();

    const int NSTAGE = HID_ / BK;   // 32
    for (int s = 0; s < NSTAGE; s++) {
        const int buf = s & 1;

        if (s < NSTAGE - 1) {
            const int k0 = (s + 1) * BK;
            #pragma unroll
            for (int i = 0; i < 4; i++) {
                const int idx = t + i * 256;
                const int row = idx >> 3, c4 = idx & 7;
                ra[i] = *(const float4*)(H + (size_t)(m0 + row) * HID_ + k0 + c4 * 4);
                rb[i] = *(const float4*)(W + (size_t)(n0 + row) * HID_ + k0 + c4 * 4);
            }
        }

        const uint32_t* A = Abuf[buf];
        const uint32_t* Bs = Bbuf[buf];
        #pragma unroll
        for (int kk = 0; kk < 4; kk++) {
            const int kb = kk * 8;
            uint32_t af[2][4], bf[8][2];
            #pragma unroll
            for (int tm = 0; tm < 2; tm++) {
                const int mb = wm * 32 + tm * 16;
                af[tm][0] = A[(kb + tig) * LDA + mb + g];
                af[tm][1] = A[(kb + tig) * LDA + mb + g + 8];
                af[tm][2] = A[(kb + tig + 4) * LDA + mb + g];
                af[tm][3] = A[(kb + tig + 4) * LDA + mb + g + 8];
            }
            #pragma unroll
            for (int tn = 0; tn < 8; tn++) {
                const int nb = wn * 64 + tn * 8;
                bf[tn][0] = Bs[(kb + tig) * LDB + nb + g];
                bf[tn][1] = Bs[(kb + tig + 4) * LDB + nb + g];
            }
            #pragma unroll
            for (int tm = 0; tm < 2; tm++)
                #pragma unroll
                for (int tn = 0; tn < 8; tn++)
                    mma_tf32(acc[tm][tn], af[tm], bf[tn]);
        }

        __syncthreads();
        if (s < NSTAGE - 1) {
            uint32_t* An = Abuf[buf ^ 1];
            uint32_t* Bn = Bbuf[buf ^ 1];
            #pragma unroll
            for (int i = 0; i < 4; i++) {
                const int idx = t + i * 256;
                const int row = idx >> 3, c4 = idx & 7;
                const int k = c4 * 4;
                An[(k + 0) * LDA + row] = f2tf32(ra[i].x);
                An[(k + 1) * LDA + row] = f2tf32(ra[i].y);
                An[(k + 2) * LDA + row] = f2tf32(ra[i].z);
                An[(k + 3) * LDA + row] = f2tf32(ra[i].w);
                Bn[(k + 0) * LDB + row] = f2tf32(rb[i].x);
                Bn[(k + 1) * LDB + row] = f2tf32(rb[i].y);
                Bn[(k + 2) * LDB + row] = f2tf32(rb[i].z);
                Bn[(k + 3) * LDB + row] = f2tf32(rb[i].w);
            }
            __syncthreads();
        }
    }

    // Epilogue: scatter to [B*NH, S, HD] with bias.
    #pragma unroll
    for (int tm = 0; tm < 2; tm++) {
        const int m = m0 + wm * 32 + tm * 16 + g;
        const int bb = m >> 11;
        const int ss = m & 2047;
        #pragma unroll
        for (int tn = 0; tn < 8; tn++) {
            const int n = n0 + wn * 64 + tn * 8 + tig * 2;
            const int h = n >> 6;
            const int d = n & 63;
            const float2 bv2 = *(const float2*)(bias + n);
            float* base = out + ((size_t)(bb * NH_ + h) * S_) * HD_ + d;
            float2 o0, o1;
            o0.x = acc[tm][tn][0] + bv2.x;
            o0.y = acc[tm][tn][1] + bv2.y;
            o1.x = acc[tm][tn][2] + bv2.x;
            o1.y = acc[tm][tn][3] + bv2.y;
            *(float2*)(base + (size_t)ss * HD_) = o0;
            *(float2*)(base + (size_t)(ss + 8) * HD_) = o1;
        }
    }
}

// ===========================================================================
// Flash attention, fp32 with packed f32x2 FMA. Grid: (S/64, B*NH). 256 thr.
// ===========================================================================
#define ATTN_SMEM (4 * 64 * 68 * 4)

extern __shared__ float s_attn[];

__global__ __launch_bounds__(256) void attn_kernel(
    const float* __restrict__ mask, float* __restrict__ out)
{
    float* Qs = s_attn;            // [d][row]
    float* Ks = Qs + 64 * 68;      // [d][col]
    float* Vs = Ks + 64 * 68;      // [k][d]
    float* Ps = Vs + 64 * 68;      // [row][k]

    const int bh = blockIdx.y;
    const int bb = bh >> 4;
    const int h  = bh & 15;
    const int q0 = blockIdx.x * 64;

    const float* Q = g_q + (size_t)bh * S_ * HD_;
    const float* K = g_k + (size_t)bh * S_ * HD_;
    const float* V = g_v + (size_t)bh * S_ * HD_;
    const float* mrow = mask + (size_t)bb * S_;

    const int t  = threadIdx.x;
    const int tx = t & 15;
    const int ty = t >> 4;

    for (int idx = t; idx < 1024; idx += 256) {
        const int row = idx >> 4;
        const int dq  = (idx & 15) * 4;
        float4 q = *(const float4*)(Q + (size_t)(q0 + row) * HD_ + dq);
        Qs[(dq + 0) * 68 + row] = q.x * 0.125f;
        Qs[(dq + 1) * 68 + row] = q.y * 0.125f;
        Qs[(dq + 2) * 68 + row] = q.z * 0.125f;
        Qs[(dq + 3) * 68 + row] = q.w * 0.125f;
    }

    float m_i[4], l_i[4];
    float2 ao[4][2];
    #pragma unroll
    for (int i = 0; i < 4; i++) {
        m_i[i] = -INFINITY;
        l_i[i] = 0.0f;
        ao[i][0] = make_float2(0.f, 0.f);
        ao[i][1] = make_float2(0.f, 0.f);
    }

    for (int kv0 = 0; kv0 < S_; kv0 += 64) {
        __syncthreads();
        for (int idx = t; idx < 1024; idx += 256) {
            const int row = idx >> 4;
            const int dq  = (idx & 15) * 4;
            float4 kv = *(const float4*)(K + (size_t)(kv0 + row) * HD_ + dq);
            Ks[(dq + 0) * 68 + row] = kv.x;
            Ks[(dq + 1) * 68 + row] = kv.y;
            Ks[(dq + 2) * 68 + row] = kv.z;
            Ks[(dq + 3) * 68 + row] = kv.w;
            float4 vv = *(const float4*)(V + (size_t)(kv0 + row) * HD_ + dq);
            *(float4*)&Vs[row * 68 + dq] = vv;
        }
        __syncthreads();

        // S-gemm (packed)
        float2 sa[4][2];
        #pragma unroll
        for (int i = 0; i < 4; i++) {
            sa[i][0] = make_float2(0.f, 0.f);
            sa[i][1] = make_float2(0.f, 0.f);
        }
        #pragma unroll 8
        for (int d = 0; d < 64; d++) {
            float av[4], bv4[4];
            *(float4*)av  = *(const float4*)&Qs[d * 68 + ty * 4];
            *(float4*)bv4 = *(const float4*)&Ks[d * 68 + tx * 4];
            const float2 b01 = make_float2(bv4[0], bv4[1]);
            const float2 b23 = make_float2(bv4[2], bv4[3]);
            #pragma unroll
            for (int i = 0; i < 4; i++) {
                const float2 ai = make_float2(av[i], av[i]);
                ffma2(sa[i][0], ai, b01);
                ffma2(sa[i][1], ai, b23);
            }
        }

        float mv[4];
        *(float4*)mv = *(const float4*)(mrow + kv0 + tx * 4);
        #pragma unroll
        for (int i = 0; i < 4; i++) {
            sa[i][0].x += mv[0]; sa[i][0].y += mv[1];
            sa[i][1].x += mv[2]; sa[i][1].y += mv[3];
        }

        // Online softmax per row
        #pragma unroll
        for (int i = 0; i < 4; i++) {
            float r = fmaxf(fmaxf(sa[i][0].x, sa[i][0].y),
                            fmaxf(sa[i][1].x, sa[i][1].y));
            r = fmaxf(r, __shfl_xor_sync(0xffffffffu, r, 1));
            r = fmaxf(r, __shfl_xor_sync(0xffffffffu, r, 2));
            r = fmaxf(r, __shfl_xor_sync(0xffffffffu, r, 4));
            r = fmaxf(r, __shfl_xor_sync(0xffffffffu, r, 8));
            const float mnew  = fmaxf(m_i[i], r);
            const float alpha = __expf(m_i[i] - mnew);
            m_i[i] = mnew;
            sa[i][0].x = __expf(sa[i][0].x - mnew);
            sa[i][0].y = __expf(sa[i][0].y - mnew);
            sa[i][1].x = __expf(sa[i][1].x - mnew);
            sa[i][1].y = __expf(sa[i][1].y - mnew);
            float sum = sa[i][0].x + sa[i][0].y + sa[i][1].x + sa[i][1].y;
            sum += __shfl_xor_sync(0xffffffffu, sum, 1);
            sum += __shfl_xor_sync(0xffffffffu, sum, 2);
            sum += __shfl_xor_sync(0xffffffffu, sum, 4);
            sum += __shfl_xor_sync(0xffffffffu, sum, 8);
            l_i[i] = l_i[i] * alpha + sum;
            ao[i][0].x *= alpha; ao[i][0].y *= alpha;
            ao[i][1].x *= alpha; ao[i][1].y *= alpha;
        }

        // Stage P
        #pragma unroll
        for (int i = 0; i < 4; i++) {
            float4 p;
            p.x = sa[i][0].x; p.y = sa[i][0].y;
            p.z = sa[i][1].x; p.w = sa[i][1].y;
            *(float4*)&Ps[(ty * 4 + i) * 68 + tx * 4] = p;
        }
        __syncthreads();

        // O-gemm (packed)
        #pragma unroll 4
        for (int k4 = 0; k4 < 16; k4++) {
            float pa[4][4];
            #pragma unroll
            for (int i = 0; i < 4; i++)
                *(float4*)pa[i] = *(const float4*)&Ps[(ty * 4 + i) * 68 + k4 * 4];
            float2 v01[4], v23[4];
            #pragma unroll
            for (int kk = 0; kk < 4; kk++) {
                float vb[4];
                *(float4*)vb = *(const float4*)&Vs[(k4 * 4 + kk) * 68 + tx * 4];
                v01[kk] = make_float2(vb[0], vb[1]);
                v23[kk] = make_float2(vb[2], vb[3]);
            }
            #pragma unroll
            for (int i = 0; i < 4; i++)
                #pragma unroll
                for (int kk = 0; kk < 4; kk++) {
                    const float2 pk = make_float2(pa[i][kk], pa[i][kk]);
                    ffma2(ao[i][0], pk, v01[kk]);
                    ffma2(ao[i][1], pk, v23[kk]);
                }
        }
    }

    #pragma unroll
    for (int i = 0; i < 4; i++) {
        const float inv = 1.0f / l_i[i];
        float4 o;
        o.x = ao[i][0].x * inv;
        o.y = ao[i][0].y * inv;
        o.z = ao[i][1].x * inv;
        o.w = ao[i][1].y * inv;
        const int ss = q0 + ty * 4 + i;
        *(float4*)(out + ((size_t)(bb * S_ + ss) * HID_) + h * 64 + tx * 4) = o;
    }
}

// ===========================================================================
extern "C" void kernel_launch(void* const* d_in, const int* in_sizes, int n_in,
                              void* d_out, int out_size)
{
    const float* H    = (const float*)d_in[0];
    const float* mask = (const float*)d_in[1];
    const float* Wq   = (const float*)d_in[2];
    const float* bq   = (const float*)d_in[3];
    const float* Wk   = (const float*)d_in[4];
    const float* bk   = (const float*)d_in[5];
    const float* Wv   = (const float*)d_in[6];
    const float* bv   = (const float*)d_in[7];
    float* out = (float*)d_out;

    cudaFuncSetAttribute(qkv_mma,
                         cudaFuncAttributeMaxDynamicSharedMemorySize, QKV_SMEM);
    cudaFuncSetAttribute(attn_kernel,
                         cudaFuncAttributeMaxDynamicSharedMemorySize, ATTN_SMEM);

    dim3 gq(HID_ / BN, (B_ * S_) / BM, 3);   // (8, 64, 3)
    qkv_mma<<<gq, 256, QKV_SMEM>>>(H, Wq, bq, Wk, bk, Wv, bv);

    dim3 ga(S_ / 64, B_ * NH_);              // (32, 64)
    attn_kernel<<<ga, 256, ATTN_SMEM>>>(mask, out);
}

// round 4
// speedup vs baseline: 2.7776x; 2.0256x over previous
#include <cuda_runtime.h>
#include <math.h>
#include <stdint.h>

#define B_ 4
#define S_ 2048
#define HID_ 1024
#define NH_ 16
#define HD_ 64

// Scratch for Q, K, V in [B*NH, S, HD] layout (32 MB each).
__device__ float g_q[B_ * NH_ * S_ * HD_];
__device__ float g_k[B_ * NH_ * S_ * HD_];
__device__ float g_v[B_ * NH_ * S_ * HD_];

// ===========================================================================
// PTX helpers (no 'a'-gated instructions: mma.sync + f32x2 only)
// ===========================================================================
__device__ __forceinline__ uint32_t f2tf32(float x) {
    uint32_t r;
    asm("cvt.rna.tf32.f32 %0, %1;" : "=r"(r) : "f"(x));
    return r;
}

__device__ __forceinline__ void mma_tf32(float* d, const uint32_t* a, const uint32_t* b) {
    asm volatile(
        "mma.sync.aligned.m16n8k8.row.col.f32.tf32.tf32.f32 "
        "{%0,%1,%2,%3}, {%4,%5,%6,%7}, {%8,%9}, {%0,%1,%2,%3};"
        : "+f"(d[0]), "+f"(d[1]), "+f"(d[2]), "+f"(d[3])
        : "r"(a[0]), "r"(a[1]), "r"(a[2]), "r"(a[3]), "r"(b[0]), "r"(b[1]));
}

__device__ __forceinline__ void mma_tf32b(float* d, const uint32_t* a,
                                          uint32_t b0, uint32_t b1) {
    asm volatile(
        "mma.sync.aligned.m16n8k8.row.col.f32.tf32.tf32.f32 "
        "{%0,%1,%2,%3}, {%4,%5,%6,%7}, {%8,%9}, {%0,%1,%2,%3};"
        : "+f"(d[0]), "+f"(d[1]), "+f"(d[2]), "+f"(d[3])
        : "r"(a[0]), "r"(a[1]), "r"(a[2]), "r"(a[3]), "r"(b0), "r"(b1));
}

// ===========================================================================
// QKV projection via mma.sync tf32. (unchanged from round 3 — known good)
// ===========================================================================
#define BM 128
#define BN 128
#define BK 32
#define LDA 132
#define LDB 132
#define A_WORDS (BK * LDA)
#define B_WORDS (BK * LDB)
#define QKV_SMEM (2 * (A_WORDS + B_WORDS) * 4)

extern __shared__ uint32_t qkv_sm[];

__global__ __launch_bounds__(256) void qkv_mma(
    const float* __restrict__ H,
    const float* __restrict__ Wq, const float* __restrict__ bq,
    const float* __restrict__ Wk, const float* __restrict__ bk,
    const float* __restrict__ Wv, const float* __restrict__ bv)
{
    const int proj = blockIdx.z;
    const float* W    = (proj == 0) ? Wq : (proj == 1) ? Wk : Wv;
    const float* bias = (proj == 0) ? bq : (proj == 1) ? bk : bv;
    float* out        = (proj == 0) ? g_q : (proj == 1) ? g_k : g_v;

    const int m0 = blockIdx.y * BM;
    const int n0 = blockIdx.x * BN;

    const int t    = threadIdx.x;
    const int lane = t & 31;
    const int wid  = t >> 5;
    const int wm   = wid & 3;
    const int wn   = wid >> 2;
    const int g    = lane >> 2;
    const int tig  = lane & 3;

    uint32_t* Abuf[2] = {qkv_sm, qkv_sm + A_WORDS};
    uint32_t* Bbuf[2] = {qkv_sm + 2 * A_WORDS, qkv_sm + 2 * A_WORDS + B_WORDS};

    float acc[2][8][4];
    #pragma unroll
    for (int i = 0; i < 2; i++)
        #pragma unroll
        for (int j = 0; j < 8; j++)
            #pragma unroll
            for (int c = 0; c < 4; c++) acc[i][j][c] = 0.0f;

    float4 ra[4], rb[4];
    #pragma unroll
    for (int i = 0; i < 4; i++) {
        const int idx = t + i * 256;
        const int row = idx >> 3, c4 = idx & 7;
        ra[i] = *(const float4*)(H + (size_t)(m0 + row) * HID_ + c4 * 4);
        rb[i] = *(const float4*)(W + (size_t)(n0 + row) * HID_ + c4 * 4);
    }
    #pragma unroll
    for (int i = 0; i < 4; i++) {
        const int idx = t + i * 256;
        const int row = idx >> 3, c4 = idx & 7;
        const int k = c4 * 4;
        Abuf[0][(k + 0) * LDA + row] = f2tf32(ra[i].x);
        Abuf[0][(k + 1) * LDA + row] = f2tf32(ra[i].y);
        Abuf[0][(k + 2) * LDA + row] = f2tf32(ra[i].z);
        Abuf[0][(k + 3) * LDA + row] = f2tf32(ra[i].w);
        Bbuf[0][(k + 0) * LDB + row] = f2tf32(rb[i].x);
        Bbuf[0][(k + 1) * LDB + row] = f2tf32(rb[i].y);
        Bbuf[0][(k + 2) * LDB + row] = f2tf32(rb[i].z);
        Bbuf[0][(k + 3) * LDB + row] = f2tf32(rb[i].w);
    }
    __syncthreads();

    const int NSTAGE = HID_ / BK;
    for (int s = 0; s < NSTAGE; s++) {
        const int buf = s & 1;

        if (s < NSTAGE - 1) {
            const int k0 = (s + 1) * BK;
            #pragma unroll
            for (int i = 0; i < 4; i++) {
                const int idx = t + i * 256;
                const int row = idx >> 3, c4 = idx & 7;
                ra[i] = *(const float4*)(H + (size_t)(m0 + row) * HID_ + k0 + c4 * 4);
                rb[i] = *(const float4*)(W + (size_t)(n0 + row) * HID_ + k0 + c4 * 4);
            }
        }

        const uint32_t* A = Abuf[buf];
        const uint32_t* Bs = Bbuf[buf];
        #pragma unroll
        for (int kk = 0; kk < 4; kk++) {
            const int kb = kk * 8;
            uint32_t af[2][4], bf[8][2];
            #pragma unroll
            for (int tm = 0; tm < 2; tm++) {
                const int mb = wm * 32 + tm * 16;
                af[tm][0] = A[(kb + tig) * LDA + mb + g];
                af[tm][1] = A[(kb + tig) * LDA + mb + g + 8];
                af[tm][2] = A[(kb + tig + 4) * LDA + mb + g];
                af[tm][3] = A[(kb + tig + 4) * LDA + mb + g + 8];
            }
            #pragma unroll
            for (int tn = 0; tn < 8; tn++) {
                const int nb = wn * 64 + tn * 8;
                bf[tn][0] = Bs[(kb + tig) * LDB + nb + g];
                bf[tn][1] = Bs[(kb + tig + 4) * LDB + nb + g];
            }
            #pragma unroll
            for (int tm = 0; tm < 2; tm++)
                #pragma unroll
                for (int tn = 0; tn < 8; tn++)
                    mma_tf32(acc[tm][tn], af[tm], bf[tn]);
        }

        __syncthreads();
        if (s < NSTAGE - 1) {
            uint32_t* An = Abuf[buf ^ 1];
            uint32_t* Bn = Bbuf[buf ^ 1];
            #pragma unroll
            for (int i = 0; i < 4; i++) {
                const int idx = t + i * 256;
                const int row = idx >> 3, c4 = idx & 7;
                const int k = c4 * 4;
                An[(k + 0) * LDA + row] = f2tf32(ra[i].x);
                An[(k + 1) * LDA + row] = f2tf32(ra[i].y);
                An[(k + 2) * LDA + row] = f2tf32(ra[i].z);
                An[(k + 3) * LDA + row] = f2tf32(ra[i].w);
                Bn[(k + 0) * LDB + row] = f2tf32(rb[i].x);
                Bn[(k + 1) * LDB + row] = f2tf32(rb[i].y);
                Bn[(k + 2) * LDB + row] = f2tf32(rb[i].z);
                Bn[(k + 3) * LDB + row] = f2tf32(rb[i].w);
            }
            __syncthreads();
        }
    }

    #pragma unroll
    for (int tm = 0; tm < 2; tm++) {
        const int m = m0 + wm * 32 + tm * 16 + g;
        const int bb = m >> 11;
        const int ss = m & 2047;
        #pragma unroll
        for (int tn = 0; tn < 8; tn++) {
            const int n = n0 + wn * 64 + tn * 8 + tig * 2;
            const int h = n >> 6;
            const int d = n & 63;
            const float2 bv2 = *(const float2*)(bias + n);
            float* base = out + ((size_t)(bb * NH_ + h) * S_) * HD_ + d;
            float2 o0, o1;
            o0.x = acc[tm][tn][0] + bv2.x;
            o0.y = acc[tm][tn][1] + bv2.y;
            o1.x = acc[tm][tn][2] + bv2.x;
            o1.y = acc[tm][tn][3] + bv2.y;
            *(float2*)(base + (size_t)ss * HD_) = o0;
            *(float2*)(base + (size_t)(ss + 8) * HD_) = o1;
        }
    }
}

// ===========================================================================
// Flash attention via mma.sync tf32.
// CTA: 256 thr (8 warps), Q tile 128 rows (16/warp), KV tile 64, HD=64.
// Q fragments in registers for the whole loop. K ld=68, V ld=72 (both
// conflict-free for their fragment access pattern). P staged per-warp.
// ===========================================================================
#define AT_BM 128
#define AT_THREADS 256
#define LDK 68
#define LDV 72
#define LDP 68

#define KS_OFF 0
#define VS_OFF (64 * LDK)
#define PS_OFF (VS_OFF + 64 * LDV)
#define MSK_OFF (PS_OFF + 8 * 16 * LDP)
#define AT_SMEM ((MSK_OFF + 64) * 4)

extern __shared__ uint32_t at_sm[];

__global__ void __launch_bounds__(AT_THREADS, 2) attn_mma(
    const float* __restrict__ mask, float* __restrict__ out)
{
    const int bh = blockIdx.y;
    const int bb = bh >> 4;
    const int h  = bh & 15;
    const int q0 = blockIdx.x * AT_BM;

    const float* Q = g_q + (size_t)bh * S_ * HD_;
    const float* K = g_k + (size_t)bh * S_ * HD_;
    const float* V = g_v + (size_t)bh * S_ * HD_;
    const float* mrow = mask + (size_t)bb * S_;

    const int t    = threadIdx.x;
    const int lane = t & 31;
    const int w    = t >> 5;
    const int g    = lane >> 2;
    const int tig  = lane & 3;

    uint32_t* Ks = at_sm + KS_OFF;
    uint32_t* Vs = at_sm + VS_OFF;
    uint32_t* Ps = at_sm + PS_OFF + w * 16 * LDP;
    float*    msk = (float*)(at_sm + MSK_OFF);

    // Q fragments, pre-scaled by 1/sqrt(64)=0.125, tf32 (kept in regs)
    uint32_t qf[8][4];
    {
        const float* q0p = Q + (size_t)(q0 + w * 16 + g) * HD_;
        const float* q1p = q0p + 8 * HD_;
        #pragma unroll
        for (int kb = 0; kb < 8; kb++) {
            qf[kb][0] = f2tf32(0.125f * q0p[kb * 8 + tig]);
            qf[kb][1] = f2tf32(0.125f * q1p[kb * 8 + tig]);
            qf[kb][2] = f2tf32(0.125f * q0p[kb * 8 + tig + 4]);
            qf[kb][3] = f2tf32(0.125f * q1p[kb * 8 + tig + 4]);
        }
    }

    float oacc[8][4];
    #pragma unroll
    for (int nt = 0; nt < 8; nt++)
        #pragma unroll
        for (int c = 0; c < 4; c++) oacc[nt][c] = 0.0f;
    float m0 = -INFINITY, m1 = -INFINITY, l0 = 0.0f, l1 = 0.0f;

    for (int kv0 = 0; kv0 < S_; kv0 += 64) {
        __syncthreads();   // all warps done reading Ks/Vs of previous tile
        #pragma unroll
        for (int i = 0; i < 4; i++) {
            const int idx = t + i * 256;
            const int r = idx >> 4, c4 = (idx & 15) * 4;
            float4 kvv = *(const float4*)(K + (size_t)(kv0 + r) * HD_ + c4);
            uint32_t* dk = Ks + r * LDK + c4;
            dk[0] = f2tf32(kvv.x); dk[1] = f2tf32(kvv.y);
            dk[2] = f2tf32(kvv.z); dk[3] = f2tf32(kvv.w);
            float4 vvv = *(const float4*)(V + (size_t)(kv0 + r) * HD_ + c4);
            uint32_t* dv = Vs + r * LDV + c4;
            dv[0] = f2tf32(vvv.x); dv[1] = f2tf32(vvv.y);
            dv[2] = f2tf32(vvv.z); dv[3] = f2tf32(vvv.w);
        }
        if (t < 16) *(float4*)&msk[t * 4] = *(const float4*)(mrow + kv0 + t * 4);
        __syncthreads();

        // S = Q K^T  (rows g/g+8, cols nt*8 + 2tig, 2tig+1)
        float sacc[8][4];
        #pragma unroll
        for (int nt = 0; nt < 8; nt++)
            #pragma unroll
            for (int c = 0; c < 4; c++) sacc[nt][c] = 0.0f;

        #pragma unroll
        for (int kb = 0; kb < 8; kb++) {
            const uint32_t* kp = Ks + g * LDK + kb * 8 + tig;
            #pragma unroll
            for (int nt = 0; nt < 8; nt++) {
                const uint32_t b0 = kp[nt * 8 * LDK];
                const uint32_t b1 = kp[nt * 8 * LDK + 4];
                mma_tf32b(sacc[nt], qf[kb], b0, b1);
            }
        }

        // mask + row stats
        float mx0 = m0, mx1 = m1;
        #pragma unroll
        for (int nt = 0; nt < 8; nt++) {
            const float2 mk = *(const float2*)&msk[nt * 8 + 2 * tig];
            sacc[nt][0] += mk.x; sacc[nt][1] += mk.y;
            sacc[nt][2] += mk.x; sacc[nt][3] += mk.y;
            mx0 = fmaxf(mx0, fmaxf(sacc[nt][0], sacc[nt][1]));
            mx1 = fmaxf(mx1, fmaxf(sacc[nt][2], sacc[nt][3]));
        }
        mx0 = fmaxf(mx0, __shfl_xor_sync(0xffffffffu, mx0, 1));
        mx0 = fmaxf(mx0, __shfl_xor_sync(0xffffffffu, mx0, 2));
        mx1 = fmaxf(mx1, __shfl_xor_sync(0xffffffffu, mx1, 1));
        mx1 = fmaxf(mx1, __shfl_xor_sync(0xffffffffu, mx1, 2));

        const float alpha0 = __expf(m0 - mx0);
        const float alpha1 = __expf(m1 - mx1);
        m0 = mx0; m1 = mx1;

        float s0 = 0.0f, s1 = 0.0f;
        #pragma unroll
        for (int nt = 0; nt < 8; nt++) {
            const float p0 = __expf(sacc[nt][0] - mx0);
            const float p1 = __expf(sacc[nt][1] - mx0);
            const float p2 = __expf(sacc[nt][2] - mx1);
            const float p3 = __expf(sacc[nt][3] - mx1);
            s0 += p0 + p1;
            s1 += p2 + p3;
            uint32_t* pr0 = Ps + g * LDP + nt * 8 + 2 * tig;
            pr0[0] = f2tf32(p0); pr0[1] = f2tf32(p1);
            uint32_t* pr1 = Ps + (g + 8) * LDP + nt * 8 + 2 * tig;
            pr1[0] = f2tf32(p2); pr1[1] = f2tf32(p3);
        }
        s0 += __shfl_xor_sync(0xffffffffu, s0, 1);
        s0 += __shfl_xor_sync(0xffffffffu, s0, 2);
        s1 += __shfl_xor_sync(0xffffffffu, s1, 1);
        s1 += __shfl_xor_sync(0xffffffffu, s1, 2);
        l0 = l0 * alpha0 + s0;
        l1 = l1 * alpha1 + s1;

        #pragma unroll
        for (int nt = 0; nt < 8; nt++) {
            oacc[nt][0] *= alpha0; oacc[nt][1] *= alpha0;
            oacc[nt][2] *= alpha1; oacc[nt][3] *= alpha1;
        }
        __syncwarp();   // P staging visible within warp

        // O += P V
        #pragma unroll
        for (int kb = 0; kb < 8; kb++) {
            uint32_t a[4];
            a[0] = Ps[g * LDP + kb * 8 + tig];
            a[1] = Ps[(g + 8) * LDP + kb * 8 + tig];
            a[2] = Ps[g * LDP + kb * 8 + tig + 4];
            a[3] = Ps[(g + 8) * LDP + kb * 8 + tig + 4];
            const uint32_t* vp = Vs + (kb * 8 + tig) * LDV + g;
            #pragma unroll
            for (int nt = 0; nt < 8; nt++) {
                const uint32_t b0 = vp[nt * 8];
                const uint32_t b1 = vp[4 * LDV + nt * 8];
                mma_tf32b(oacc[nt], a, b0, b1);
            }
        }
    }

    // Epilogue
    const float inv0 = 1.0f / l0;
    const float inv1 = 1.0f / l1;
    const int r0 = q0 + w * 16 + g;
    float* o0 = out + ((size_t)(bb * S_ + r0)) * HID_ + h * 64;
    float* o1 = out + ((size_t)(bb * S_ + r0 + 8)) * HID_ + h * 64;
    #pragma unroll
    for (int nt = 0; nt < 8; nt++) {
        const int c = nt * 8 + 2 * tig;
        float2 v0, v1;
        v0.x = oacc[nt][0] * inv0; v0.y = oacc[nt][1] * inv0;
        v1.x = oacc[nt][2] * inv1; v1.y = oacc[nt][3] * inv1;
        *(float2*)(o0 + c) = v0;
        *(float2*)(o1 + c) = v1;
    }
}

// ===========================================================================
extern "C" void kernel_launch(void* const* d_in, const int* in_sizes, int n_in,
                              void* d_out, int out_size)
{
    const float* H    = (const float*)d_in[0];
    const float* mask = (const float*)d_in[1];
    const float* Wq   = (const float*)d_in[2];
    const float* bq   = (const float*)d_in[3];
    const float* Wk   = (const float*)d_in[4];
    const float* bk   = (const float*)d_in[5];
    const float* Wv   = (const float*)d_in[6];
    const float* bv   = (const float*)d_in[7];
    float* out = (float*)d_out;

    cudaFuncSetAttribute(qkv_mma,
                         cudaFuncAttributeMaxDynamicSharedMemorySize, QKV_SMEM);
    cudaFuncSetAttribute(attn_mma,
                         cudaFuncAttributeMaxDynamicSharedMemorySize, AT_SMEM);

    dim3 gq(HID_ / BN, (B_ * S_) / BM, 3);   // (8, 64, 3)
    qkv_mma<<<gq, 256, QKV_SMEM>>>(H, Wq, bq, Wk, bk, Wv, bv);

    dim3 ga(S_ / AT_BM, B_ * NH_);           // (16, 64)
    attn_mma<<<ga, AT_THREADS, AT_SMEM>>>(mask, out);
}

// round 5
// speedup vs baseline: 3.6188x; 1.3028x over previous
#include <cuda_runtime.h>
#include <math.h>
#include <stdint.h>

#define B_ 4
#define S_ 2048
#define HID_ 1024
#define NH_ 16
#define HD_ 64
#define LOG2E 1.4426950408889634f

// Scratch: rounded inputs + Q/K/V in [B*NH, S, HD] layout.
__device__ float g_h[B_ * S_ * HID_];        // rna-rounded H (32 MB)
__device__ float g_w[3][HID_ * HID_];        // rna-rounded Wq/Wk/Wv (12 MB)
__device__ float g_q[B_ * NH_ * S_ * HD_];
__device__ float g_k[B_ * NH_ * S_ * HD_];
__device__ float g_v[B_ * NH_ * S_ * HD_];

// ===========================================================================
// PTX helpers (sm_103 base ISA only)
// ===========================================================================
__device__ __forceinline__ uint32_t smem_u32(const void* p) {
    uint32_t a;
    asm("{ .reg .u64 t; cvta.to.shared.u64 t, %1; cvt.u32.u64 %0, t; }"
        : "=r"(a) : "l"(p));
    return a;
}

__device__ __forceinline__ uint32_t f2tf32(float x) {
    uint32_t r;
    asm("cvt.rna.tf32.f32 %0, %1;" : "=r"(r) : "f"(x));
    return r;
}

__device__ __forceinline__ float ex2(float x) {
    float r;
    asm("ex2.approx.f32 %0, %1;" : "=f"(r) : "f"(x));
    return r;
}

__device__ __forceinline__ void mma_tf32(float* d, const uint32_t* a, const uint32_t* b) {
    asm volatile(
        "mma.sync.aligned.m16n8k8.row.col.f32.tf32.tf32.f32 "
        "{%0,%1,%2,%3}, {%4,%5,%6,%7}, {%8,%9}, {%0,%1,%2,%3};"
        : "+f"(d[0]), "+f"(d[1]), "+f"(d[2]), "+f"(d[3])
        : "r"(a[0]), "r"(a[1]), "r"(a[2]), "r"(a[3]), "r"(b[0]), "r"(b[1]));
}

__device__ __forceinline__ void mma_tf32b(float* d, const uint32_t* a,
                                          uint32_t b0, uint32_t b1) {
    asm volatile(
        "mma.sync.aligned.m16n8k8.row.col.f32.tf32.tf32.f32 "
        "{%0,%1,%2,%3}, {%4,%5,%6,%7}, {%8,%9}, {%0,%1,%2,%3};"
        : "+f"(d[0]), "+f"(d[1]), "+f"(d[2]), "+f"(d[3])
        : "r"(a[0]), "r"(a[1]), "r"(a[2]), "r"(a[3]), "r"(b0), "r"(b1));
}

__device__ __forceinline__ void cp16(uint32_t dst, const void* src) {
    asm volatile("cp.async.cg.shared.global [%0], [%1], 16;"
                 :: "r"(dst), "l"(src) : "memory");
}
#define CP_COMMIT() asm volatile("cp.async.commit_group;" ::: "memory")
#define CP_WAIT1()  asm volatile("cp.async.wait_group 1;" ::: "memory")

__device__ __forceinline__ void mulf2(float2& d, float a) {
    float2 s = make_float2(a, a);
    asm("mul.rn.f32x2 %0, %0, %1;"
        : "+l"(*reinterpret_cast<unsigned long long*>(&d))
        : "l"(*reinterpret_cast<const unsigned long long*>(&s)));
}

// ===========================================================================
// Prologue: rna-round H and W into scratch (makes tf32 truncation exact).
// One float4 per thread.
// ===========================================================================
#define HN4 (B_ * S_ * HID_ / 4)      // 2097152
#define WN4 (HID_ * HID_ / 4)         // 262144
#define RND_BLOCKS ((HN4 + 3 * WN4) / 256)

__global__ __launch_bounds__(256) void round_inputs(
    const float* __restrict__ H, const float* __restrict__ Wq,
    const float* __restrict__ Wk, const float* __restrict__ Wv)
{
    const int i = blockIdx.x * 256 + threadIdx.x;
    const float* src;
    float* dst;
    int j = i;
    if (j < HN4) { src = H; dst = g_h; }
    else if ((j -= HN4) < WN4) { src = Wq; dst = g_w[0]; }
    else if ((j -= WN4) < WN4) { src = Wk; dst = g_w[1]; }
    else { j -= WN4; src = Wv; dst = g_w[2]; }
    float4 v = ((const float4*)src)[j];
    uint4 o;
    o.x = f2tf32(v.x); o.y = f2tf32(v.y);
    o.z = f2tf32(v.z); o.w = f2tf32(v.w);
    ((uint4*)dst)[j] = o;
}

// ===========================================================================
// QKV projection via mma.sync tf32 + cp.async 3-stage pipeline.
// CTA 128x128, BK=32, 256 thr (8 warps, warp tile 32x64).
// Smem layout [row][k], 36 words/row (32 + 4 pad) -> conflict-free fragments.
// ===========================================================================
#define QLDA 36
#define QSTG_W (128 * QLDA)           // 4608 words/stage/matrix
#define QB_OFF (3 * QSTG_W)           // 13824
#define QKV_SMEM (6 * QSTG_W * 4)     // 110592 B

extern __shared__ uint32_t qkv_sm[];

__global__ __launch_bounds__(256) void qkv_mma(
    const float* __restrict__ bq, const float* __restrict__ bk,
    const float* __restrict__ bv)
{
    const int proj = blockIdx.z;
    const float* Wsel = g_w[proj];
    const float* bias = (proj == 0) ? bq : (proj == 1) ? bk : bv;
    float* out        = (proj == 0) ? g_q : (proj == 1) ? g_k : g_v;

    const int m0 = blockIdx.y * 128;
    const int n0 = blockIdx.x * 128;

    const int t    = threadIdx.x;
    const int lane = t & 31;
    const int wid  = t >> 5;
    const int wm   = wid & 3;
    const int wn   = wid >> 2;
    const int g    = lane >> 2;
    const int tig  = lane & 3;

    const uint32_t sbase = smem_u32(qkv_sm);

    float acc[2][8][4];
    #pragma unroll
    for (int i = 0; i < 2; i++)
        #pragma unroll
        for (int j = 0; j < 8; j++)
            #pragma unroll
            for (int c = 0; c < 4; c++) acc[i][j][c] = 0.0f;

    // cp.async one stage (st) into smem slot
    auto cp_stage = [&](int st, int slot) {
        const int k0 = st * 32;
        const float* hA = g_h + (size_t)m0 * HID_ + k0;
        const float* wB = Wsel + (size_t)n0 * HID_ + k0;
        #pragma unroll
        for (int j = 0; j < 4; j++) {
            const int c = t + j * 256;
            const int r = c >> 3, cc = (c & 7) * 4;
            cp16(sbase + (uint32_t)(slot * QSTG_W + r * QLDA + cc) * 4,
                 hA + (size_t)r * HID_ + cc);
            cp16(sbase + (uint32_t)(QB_OFF + slot * QSTG_W + r * QLDA + cc) * 4,
                 wB + (size_t)r * HID_ + cc);
        }
    };

    cp_stage(0, 0); CP_COMMIT();
    cp_stage(1, 1); CP_COMMIT();

    for (int s = 0; s < 32; s++) {
        CP_WAIT1();
        __syncthreads();
        if (s + 2 < 32) cp_stage(s + 2, (s + 2) % 3);
        CP_COMMIT();

        const uint32_t* A  = qkv_sm + (s % 3) * QSTG_W;
        const uint32_t* Bs = qkv_sm + QB_OFF + (s % 3) * QSTG_W;

        #pragma unroll
        for (int kk = 0; kk < 4; kk++) {
            const int kb = kk * 8;
            uint32_t af[2][4], bf[8][2];
            #pragma unroll
            for (int tm = 0; tm < 2; tm++) {
                const int mr = wm * 32 + tm * 16;
                af[tm][0] = A[(mr + g) * QLDA + kb + tig];
                af[tm][1] = A[(mr + g + 8) * QLDA + kb + tig];
                af[tm][2] = A[(mr + g) * QLDA + kb + tig + 4];
                af[tm][3] = A[(mr + g + 8) * QLDA + kb + tig + 4];
            }
            #pragma unroll
            for (int tn = 0; tn < 8; tn++) {
                const int nr = wn * 64 + tn * 8;
                bf[tn][0] = Bs[(nr + g) * QLDA + kb + tig];
                bf[tn][1] = Bs[(nr + g) * QLDA + kb + tig + 4];
            }
            #pragma unroll
            for (int tm = 0; tm < 2; tm++)
                #pragma unroll
                for (int tn = 0; tn < 8; tn++)
                    mma_tf32(acc[tm][tn], af[tm], bf[tn]);
        }
    }

    // Epilogue: rna-round outputs so attn's cp.async->tf32 truncation is exact.
    #pragma unroll
    for (int tm = 0; tm < 2; tm++) {
        const int m = m0 + wm * 32 + tm * 16 + g;
        const int bb = m >> 11;
        const int ss = m & 2047;
        #pragma unroll
        for (int tn = 0; tn < 8; tn++) {
            const int n = n0 + wn * 64 + tn * 8 + tig * 2;
            const int h = n >> 6;
            const int d = n & 63;
            const float2 bv2 = *(const float2*)(bias + n);
            float* base = out + ((size_t)(bb * NH_ + h) * S_) * HD_ + d;
            float2 o0, o1;
            o0.x = __uint_as_float(f2tf32(acc[tm][tn][0] + bv2.x));
            o0.y = __uint_as_float(f2tf32(acc[tm][tn][1] + bv2.y));
            o1.x = __uint_as_float(f2tf32(acc[tm][tn][2] + bv2.x));
            o1.y = __uint_as_float(f2tf32(acc[tm][tn][3] + bv2.y));
            *(float2*)(base + (size_t)ss * HD_) = o0;
            *(float2*)(base + (size_t)(ss + 8) * HD_) = o1;
        }
    }
}

// ===========================================================================
// Flash attention via mma.sync tf32 + cp.async double-buffered K/V.
// CTA: 256 thr (8 warps), Q tile 128 rows (16/warp), KV tile 64, HD=64.
// exp2-domain softmax; full mask staged in smem (scaled by log2e).
// Smem words: KS[2]@0/4352, VS[2]@8704/13056, PS@17408 (+w*1088), MSK@26112.
// ===========================================================================
#define LDK 68
#define LDV 68
#define LDP 68
#define KVBUF_W 4352                   // 64*68
#define VS_OFF 8704
#define PS_OFF 17408
#define MSK_OFF 26112
#define AT_SMEM ((MSK_OFF + 2048) * 4) // 112640 B

extern __shared__ uint32_t at_sm[];

__global__ void __launch_bounds__(256, 2) attn_mma(
    const float* __restrict__ mask, float* __restrict__ out)
{
    const int bh = blockIdx.y;
    const int bb = bh >> 4;
    const int h  = bh & 15;
    const int q0 = blockIdx.x * 128;

    const float* Q = g_q + (size_t)bh * S_ * HD_;
    const float* K = g_k + (size_t)bh * S_ * HD_;
    const float* V = g_v + (size_t)bh * S_ * HD_;
    const float* mrow = mask + (size_t)bb * S_;

    const int t    = threadIdx.x;
    const int lane = t & 31;
    const int w    = t >> 5;
    const int g    = lane >> 2;
    const int tig  = lane & 3;

    const uint32_t sbase = smem_u32(at_sm);
    float* msk = (float*)(at_sm + MSK_OFF);

    // Stage full mask, pre-scaled by log2e (exp2 domain).
    #pragma unroll
    for (int i = t; i < 512; i += 256) {
        float4 m4 = ((const float4*)mrow)[i];
        m4.x *= LOG2E; m4.y *= LOG2E; m4.z *= LOG2E; m4.w *= LOG2E;
        ((float4*)msk)[i] = m4;
    }

    // Q fragments: scaled by (1/8)*log2e, rna-rounded, kept in regs.
    const float SC = 0.125f * LOG2E;
    uint32_t qf[8][4];
    {
        const float* q0p = Q + (size_t)(q0 + w * 16 + g) * HD_;
        const float* q1p = q0p + 8 * HD_;
        #pragma unroll
        for (int kb = 0; kb < 8; kb++) {
            qf[kb][0] = f2tf32(SC * q0p[kb * 8 + tig]);
            qf[kb][1] = f2tf32(SC * q1p[kb * 8 + tig]);
            qf[kb][2] = f2tf32(SC * q0p[kb * 8 + tig + 4]);
            qf[kb][3] = f2tf32(SC * q1p[kb * 8 + tig + 4]);
        }
    }

    // cp.async one KV tile into buffer
    auto cp_tile = [&](int tile, int buf) {
        const int kv0 = tile * 64;
        #pragma unroll
        for (int j = 0; j < 4; j++) {
            const int c = t + j * 256;
            const int r = c >> 4, cc = (c & 15) * 4;
            cp16(sbase + (uint32_t)(buf * KVBUF_W + r * LDK + cc) * 4,
                 K + (size_t)(kv0 + r) * HD_ + cc);
            cp16(sbase + (uint32_t)(VS_OFF + buf * KVBUF_W + r * LDV + cc) * 4,
                 V + (size_t)(kv0 + r) * HD_ + cc);
        }
    };

    cp_tile(0, 0); CP_COMMIT();

    float2 oa[8][2];
    #pragma unroll
    for (int nt = 0; nt < 8; nt++) {
        oa[nt][0] = make_float2(0.f, 0.f);
        oa[nt][1] = make_float2(0.f, 0.f);
    }
    float m0 = -INFINITY, m1 = -INFINITY, l0 = 0.0f, l1 = 0.0f;

    for (int it = 0; it < 32; it++) {
        const int buf = it & 1;
        if (it + 1 < 32) cp_tile(it + 1, buf ^ 1);
        CP_COMMIT();
        CP_WAIT1();
        __syncthreads();

        const uint32_t* Ks = at_sm + buf * KVBUF_W;
        const uint32_t* Vs = at_sm + VS_OFF + buf * KVBUF_W;
        uint32_t* Ps = at_sm + PS_OFF + w * (16 * LDP);
        const float* mk_s = msk + it * 64;

        // S = Q K^T (log2 domain)
        float sacc[8][4];
        #pragma unroll
        for (int nt = 0; nt < 8; nt++)
            #pragma unroll
            for (int c = 0; c < 4; c++) sacc[nt][c] = 0.0f;

        #pragma unroll
        for (int kb = 0; kb < 8; kb++) {
            const uint32_t* kp = Ks + g * LDK + kb * 8 + tig;
            #pragma unroll
            for (int nt = 0; nt < 8; nt++)
                mma_tf32b(sacc[nt], qf[kb],
                          kp[nt * 8 * LDK], kp[nt * 8 * LDK + 4]);
        }

        // mask + row max
        float mx0 = m0, mx1 = m1;
        #pragma unroll
        for (int nt = 0; nt < 8; nt++) {
            const float2 mk = *(const float2*)&mk_s[nt * 8 + 2 * tig];
            sacc[nt][0] += mk.x; sacc[nt][1] += mk.y;
            sacc[nt][2] += mk.x; sacc[nt][3] += mk.y;
            mx0 = fmaxf(mx0, fmaxf(sacc[nt][0], sacc[nt][1]));
            mx1 = fmaxf(mx1, fmaxf(sacc[nt][2], sacc[nt][3]));
        }
        mx0 = fmaxf(mx0, __shfl_xor_sync(0xffffffffu, mx0, 1));
        mx0 = fmaxf(mx0, __shfl_xor_sync(0xffffffffu, mx0, 2));
        mx1 = fmaxf(mx1, __shfl_xor_sync(0xffffffffu, mx1, 1));
        mx1 = fmaxf(mx1, __shfl_xor_sync(0xffffffffu, mx1, 2));

        const float alpha0 = ex2(m0 - mx0);
        const float alpha1 = ex2(m1 - mx1);
        m0 = mx0; m1 = mx1;

        float s0 = 0.0f, s1 = 0.0f;
        #pragma unroll
        for (int nt = 0; nt < 8; nt++) {
            // rna-round p; sum the ROUNDED p so O/l stays unbiased
            const uint32_t u0 = f2tf32(ex2(sacc[nt][0] - mx0));
            const uint32_t u1 = f2tf32(ex2(sacc[nt][1] - mx0));
            const uint32_t u2 = f2tf32(ex2(sacc[nt][2] - mx1));
            const uint32_t u3 = f2tf32(ex2(sacc[nt][3] - mx1));
            s0 += __uint_as_float(u0) + __uint_as_float(u1);
            s1 += __uint_as_float(u2) + __uint_as_float(u3);
            *(uint2*)&Ps[g * LDP + nt * 8 + 2 * tig] = make_uint2(u0, u1);
            *(uint2*)&Ps[(g + 8) * LDP + nt * 8 + 2 * tig] = make_uint2(u2, u3);
        }
        s0 += __shfl_xor_sync(0xffffffffu, s0, 1);
        s0 += __shfl_xor_sync(0xffffffffu, s0, 2);
        s1 += __shfl_xor_sync(0xffffffffu, s1, 1);
        s1 += __shfl_xor_sync(0xffffffffu, s1, 2);
        l0 = l0 * alpha0 + s0;
        l1 = l1 * alpha1 + s1;

        #pragma unroll
        for (int nt = 0; nt < 8; nt++) {
            mulf2(oa[nt][0], alpha0);
            mulf2(oa[nt][1], alpha1);
        }
        __syncwarp();

        // O += P V
        #pragma unroll
        for (int kb = 0; kb < 8; kb++) {
            uint32_t a[4];
            a[0] = Ps[g * LDP + kb * 8 + tig];
            a[1] = Ps[(g + 8) * LDP + kb * 8 + tig];
            a[2] = Ps[g * LDP + kb * 8 + tig + 4];
            a[3] = Ps[(g + 8) * LDP + kb * 8 + tig + 4];
            const uint32_t* vp = Vs + (kb * 8 + tig) * LDV + g;
            #pragma unroll
            for (int nt = 0; nt < 8; nt++)
                mma_tf32b((float*)&oa[nt][0], a,
                          vp[nt * 8], vp[4 * LDV + nt * 8]);
        }
        __syncthreads();
    }

    // Epilogue
    const float inv0 = 1.0f / l0;
    const float inv1 = 1.0f / l1;
    const int r0 = q0 + w * 16 + g;
    float* o0 = out + ((size_t)(bb * S_ + r0)) * HID_ + h * 64;
    float* o1 = out + ((size_t)(bb * S_ + r0 + 8)) * HID_ + h * 64;
    #pragma unroll
    for (int nt = 0; nt < 8; nt++) {
        const int c = nt * 8 + 2 * tig;
        float2 v0, v1;
        v0.x = oa[nt][0].x * inv0; v0.y = oa[nt][0].y * inv0;
        v1.x = oa[nt][1].x * inv1; v1.y = oa[nt][1].y * inv1;
        *(float2*)(o0 + c) = v0;
        *(float2*)(o1 + c) = v1;
    }
}

// ===========================================================================
extern "C" void kernel_launch(void* const* d_in, const int* in_sizes, int n_in,
                              void* d_out, int out_size)
{
    const float* H    = (const float*)d_in[0];
    const float* mask = (const float*)d_in[1];
    const float* Wq   = (const float*)d_in[2];
    const float* bq   = (const float*)d_in[3];
    const float* Wk   = (const float*)d_in[4];
    const float* bk   = (const float*)d_in[5];
    const float* Wv   = (const float*)d_in[6];
    const float* bv   = (const float*)d_in[7];
    float* out = (float*)d_out;

    cudaFuncSetAttribute(qkv_mma,
                         cudaFuncAttributeMaxDynamicSharedMemorySize, QKV_SMEM);
    cudaFuncSetAttribute(attn_mma,
                         cudaFuncAttributeMaxDynamicSharedMemorySize, AT_SMEM);

    round_inputs<<<RND_BLOCKS, 256>>>(H, Wq, Wk, Wv);

    dim3 gq(HID_ / 128, (B_ * S_) / 128, 3);   // (8, 64, 3)
    qkv_mma<<<gq, 256, QKV_SMEM>>>(bq, bk, bv);

    dim3 ga(S_ / 128, B_ * NH_);               // (16, 64)
    attn_mma<<<ga, 256, AT_SMEM>>>(mask, out);
}